// round 1
// baseline (speedup 1.0000x reference)
#include <cuda_runtime.h>
#include <math.h>

#define N_NODES_MAX 50000
#define F 64
#define NEG 0.01f

// ---- scratch (static device globals; no allocation at runtime) ----
__device__ float  g_ssrc[N_NODES_MAX];
__device__ float  g_sdst[N_NODES_MAX];
__device__ float  g_emax[N_NODES_MAX];
__device__ float  g_denom[N_NODES_MAX];
__device__ float4 g_num[N_NODES_MAX * 16];   // [N, 64] as float4 rows

// K1: per-node attention scores + scratch init
__global__ void k_node_init(const float4* __restrict__ feat4,
                            const float*  __restrict__ attw,
                            int n)
{
    int i = blockIdx.x * blockDim.x + threadIdx.x;
    if (i >= n) return;

    float as = 0.f, ad = 0.f;
#pragma unroll
    for (int q = 0; q < 16; q++) {
        float4 f = feat4[i * 16 + q];
        as += f.x * __ldg(&attw[q * 4 + 0]) + f.y * __ldg(&attw[q * 4 + 1])
            + f.z * __ldg(&attw[q * 4 + 2]) + f.w * __ldg(&attw[q * 4 + 3]);
        ad += f.x * __ldg(&attw[64 + q * 4 + 0]) + f.y * __ldg(&attw[64 + q * 4 + 1])
            + f.z * __ldg(&attw[64 + q * 4 + 2]) + f.w * __ldg(&attw[64 + q * 4 + 3]);
    }
    g_ssrc[i] = as;
    g_sdst[i] = ad;
    g_emax[i] = -INFINITY;
    g_denom[i] = 0.f;
    float4 z = make_float4(0.f, 0.f, 0.f, 0.f);
#pragma unroll
    for (int q = 0; q < 16; q++) g_num[i * 16 + q] = z;
}

// K2: per-edge leaky_relu score + float atomic-max into emax[dst]
__global__ void k_edge_max(const int* __restrict__ src,
                           const int* __restrict__ dst,
                           int E)
{
    int e = blockIdx.x * blockDim.x + threadIdx.x;
    if (e >= E) return;
    int s = src[e], d = dst[e];
    float v = g_ssrc[s] + g_sdst[d];
    v = v > 0.f ? v : NEG * v;
    // ordered-float atomic max via int/uint trick (emax init = -inf)
    if (v >= 0.f) atomicMax((int*)&g_emax[d], __float_as_int(v));
    else          atomicMin((unsigned int*)&g_emax[d], __float_as_uint(v));
}

// K3: per-edge exp + weighted scatter-add of feature[src] into num[dst].
// 16 lanes per edge, one float4 per lane -> coalesced 256B gather + vector RED.
__global__ void k_edge_acc(const float4* __restrict__ feat4,
                           const int*    __restrict__ src,
                           const int*    __restrict__ dst,
                           int E)
{
    long long t = (long long)blockIdx.x * blockDim.x + threadIdx.x;
    int e = (int)(t >> 4);
    if (e >= E) return;
    int q = (int)(t & 15);

    int s = src[e], d = dst[e];
    float v = g_ssrc[s] + g_sdst[d];
    v = v > 0.f ? v : NEG * v;
    float ex = __expf(v - g_emax[d]);

    if (q == 0) atomicAdd(&g_denom[d], ex);

    float4 f = feat4[s * 16 + q];
    float4 add = make_float4(ex * f.x, ex * f.y, ex * f.z, ex * f.w);
    atomicAdd(&g_num[d * 16 + q], add);   // sm_90+ vector RED.ADD.v4.f32
}

// K4: h = relu(concat(feature, num/denom) @ W^T + b)
// One thread per node, all 64 outputs in registers. W cached in shared (32KB).
__global__ void k_out(const float4* __restrict__ feat4,
                      const float*  __restrict__ lin_w,   // [64, 128] row-major
                      const float*  __restrict__ lin_b,   // [64]
                      float*        __restrict__ out,     // [n, 64]
                      int n)
{
    __shared__ float4 sh_w[64 * 32];   // w[o][k] rows of 128 floats = 32 float4
    for (int i = threadIdx.x; i < 64 * 32; i += blockDim.x)
        sh_w[i] = ((const float4*)lin_w)[i];
    __syncthreads();

    int node = blockIdx.x * blockDim.x + threadIdx.x;
    if (node >= n) return;

    float den = g_denom[node];
    float inv = den > 0.f ? 1.f / den : 0.f;

    float acc[64];
#pragma unroll
    for (int o = 0; o < 64; o++) acc[o] = __ldg(&lin_b[o]);

    // first 64 input dims: feature
    for (int kq = 0; kq < 16; kq++) {
        float4 in = feat4[node * 16 + kq];
#pragma unroll
        for (int o = 0; o < 64; o++) {
            float4 w = sh_w[o * 32 + kq];
            acc[o] += in.x * w.x + in.y * w.y + in.z * w.z + in.w * w.w;
        }
    }
    // second 64 input dims: hm = num * inv
    for (int kq = 0; kq < 16; kq++) {
        float4 m = g_num[node * 16 + kq];
        float4 in = make_float4(m.x * inv, m.y * inv, m.z * inv, m.w * inv);
#pragma unroll
        for (int o = 0; o < 64; o++) {
            float4 w = sh_w[o * 32 + 16 + kq];
            acc[o] += in.x * w.x + in.y * w.y + in.z * w.z + in.w * w.w;
        }
    }

    float4* out4 = (float4*)(out + (size_t)node * 64);
#pragma unroll
    for (int q = 0; q < 16; q++) {
        float4 r;
        r.x = fmaxf(acc[q * 4 + 0], 0.f);
        r.y = fmaxf(acc[q * 4 + 1], 0.f);
        r.z = fmaxf(acc[q * 4 + 2], 0.f);
        r.w = fmaxf(acc[q * 4 + 3], 0.f);
        out4[q] = r;
    }
}

extern "C" void kernel_launch(void* const* d_in, const int* in_sizes, int n_in,
                              void* d_out, int out_size)
{
    const float* feature = (const float*)d_in[0];   // [N, 64]
    const float* attn_w  = (const float*)d_in[1];   // [128, 1]
    const float* lin_w   = (const float*)d_in[2];   // [64, 128]
    const float* lin_b   = (const float*)d_in[3];   // [64]
    const int*   src     = (const int*)d_in[4];     // [E]
    const int*   dst     = (const int*)d_in[5];     // [E]

    int n = in_sizes[0] / F;
    int E = in_sizes[4];

    const float4* feat4 = (const float4*)feature;

    {
        int threads = 256;
        int blocks = (n + threads - 1) / threads;
        k_node_init<<<blocks, threads>>>(feat4, attn_w, n);
    }
    {
        int threads = 256;
        int blocks = (E + threads - 1) / threads;
        k_edge_max<<<blocks, threads>>>(src, dst, E);
    }
    {
        int threads = 256;
        long long total = (long long)E * 16;
        int blocks = (int)((total + threads - 1) / threads);
        k_edge_acc<<<blocks, threads>>>(feat4, src, dst, E);
    }
    {
        int threads = 256;
        int blocks = (n + threads - 1) / threads;
        k_out<<<blocks, threads>>>(feat4, lin_w, lin_b, (float*)d_out, n);
    }
}